// round 2
// baseline (speedup 1.0000x reference)
#include <cuda_runtime.h>
#include <math.h>

// ---- problem dims (fixed) ----
#define Bb   2
#define Ss   1024
#define Tt   2048          // B*S tokens
#define Hh   1024
#define NHh  16
#define HDd  64
#define Ee   8
#define Ii   2048
#define NSLOT (Tt*2)       // total (token, expert) pairs = 4096

// ---- scratch (device globals; no allocations allowed) ----
__device__ float g_xn[Tt*Hh];
__device__ float g_q [Tt*Hh];
__device__ float g_k [Tt*Hh];
__device__ float g_v [Tt*Hh];
__device__ float g_ao[Tt*Hh];    // attention output (pre-WO)
__device__ float g_h [Tt*Hh];    // residual after attention
__device__ float g_hn[Tt*Hh];    // ffn-normed
__device__ float g_act[NSLOT*Ii];  // swiglu activations per slot
__device__ float g_y  [NSLOT*Hh];  // expert outputs per slot
__device__ int   g_topi[Tt*2];
__device__ float g_topw[Tt*2];
__device__ int   g_slot[Tt*2];
__device__ int   g_tok [NSLOT];
__device__ int   g_cnt [Ee];
__device__ int   g_off [Ee];
__device__ int   g_fill[Ee];

// ---------------- elementwise / small kernels ----------------

__global__ void k_zero() {
    int i = threadIdx.x;
    if (i < Ee) { g_cnt[i] = 0; g_fill[i] = 0; }
}

// one block (256 thr) per token row; each thread one float4
__global__ void k_rmsnorm(const float* __restrict__ x, const float* __restrict__ w,
                          float* __restrict__ out) {
    int t = blockIdx.x;
    int i = threadIdx.x;
    const float4* xr = (const float4*)(x + (size_t)t * Hh);
    float4 v = xr[i];
    float ss = v.x*v.x + v.y*v.y + v.z*v.z + v.w*v.w;
    __shared__ float red[256];
    red[i] = ss; __syncthreads();
    for (int s = 128; s > 0; s >>= 1) {
        if (i < s) red[i] += red[i + s];
        __syncthreads();
    }
    float rinv = rsqrtf(red[0] * (1.0f / Hh) + 1e-6f);
    float4 wv = ((const float4*)w)[i];
    float4 o;
    o.x = v.x * rinv * wv.x; o.y = v.y * rinv * wv.y;
    o.z = v.z * rinv * wv.z; o.w = v.w * rinv * wv.w;
    ((float4*)(out + (size_t)t * Hh))[i] = o;
}

// RoPE in place on q and k (gridDim.y selects tensor)
__global__ void k_rope(const float* __restrict__ fc) {
    int idx = blockIdx.x * blockDim.x + threadIdx.x;   // pair index
    float* X = (blockIdx.y == 0) ? g_q : g_k;
    int j    = idx & 31;
    int head = (idx >> 5) & (NHh - 1);
    int t    = idx >> 9;
    if (t >= Tt) return;
    int s = t & (Ss - 1);
    float2* p = (float2*)(X + (size_t)t * Hh + head * HDd + 2 * j);
    float2 ab = *p;
    float cr = fc[s * HDd + 2 * j];
    float ci = fc[s * HDd + 2 * j + 1];
    float2 o;
    o.x = ab.x * cr - ab.y * ci;
    o.y = ab.x * ci + ab.y * cr;
    *p = o;
}

// ---------------- SGEMM core (64x64x16 tiles, 256 thr, 4x4/thr) ----------------
#define BM 64
#define BN 64
#define BK 16

// QKV: C = xn @ {wq,wk,wv} selected by blockIdx.z
__global__ void k_qkv(const float* __restrict__ wq, const float* __restrict__ wk,
                      const float* __restrict__ wv) {
    const float* Bm = (blockIdx.z == 0) ? wq : (blockIdx.z == 1) ? wk : wv;
    float* C = (blockIdx.z == 0) ? g_q : (blockIdx.z == 1) ? g_k : g_v;
    const float* A = g_xn;
    __shared__ float As[BK][BM];
    __shared__ float Bs[BK][BN];
    int tx = threadIdx.x, ty = threadIdx.y;
    int tid = ty * 16 + tx;
    int arow = tid >> 2, acol = (tid & 3) * 4;
    int brow = tid >> 4, bcol = (tid & 15) * 4;
    int rowBase = blockIdx.y * BM, colBase = blockIdx.x * BN;
    float acc[4][4] = {};
    for (int k0 = 0; k0 < Hh; k0 += BK) {
        float4 a = *(const float4*)(A + (size_t)(rowBase + arow) * Hh + k0 + acol);
        As[acol+0][arow] = a.x; As[acol+1][arow] = a.y;
        As[acol+2][arow] = a.z; As[acol+3][arow] = a.w;
        *(float4*)&Bs[brow][bcol] =
            *(const float4*)(Bm + (size_t)(k0 + brow) * Hh + colBase + bcol);
        __syncthreads();
        #pragma unroll
        for (int kk = 0; kk < BK; kk++) {
            float4 av = *(float4*)&As[kk][ty * 4];
            float4 bv = *(float4*)&Bs[kk][tx * 4];
            float ar[4] = {av.x, av.y, av.z, av.w};
            float br[4] = {bv.x, bv.y, bv.z, bv.w};
            #pragma unroll
            for (int i = 0; i < 4; i++)
                #pragma unroll
                for (int j = 0; j < 4; j++) acc[i][j] += ar[i] * br[j];
        }
        __syncthreads();
    }
    #pragma unroll
    for (int i = 0; i < 4; i++) {
        float4 o = make_float4(acc[i][0], acc[i][1], acc[i][2], acc[i][3]);
        *(float4*)(C + (size_t)(rowBase + ty * 4 + i) * Hh + colBase + tx * 4) = o;
    }
}

// WO with residual: h = x + ao @ wo
__global__ void k_wo(const float* __restrict__ wo, const float* __restrict__ x) {
    const float* A = g_ao;
    __shared__ float As[BK][BM];
    __shared__ float Bs[BK][BN];
    int tx = threadIdx.x, ty = threadIdx.y;
    int tid = ty * 16 + tx;
    int arow = tid >> 2, acol = (tid & 3) * 4;
    int brow = tid >> 4, bcol = (tid & 15) * 4;
    int rowBase = blockIdx.y * BM, colBase = blockIdx.x * BN;
    float acc[4][4] = {};
    for (int k0 = 0; k0 < Hh; k0 += BK) {
        float4 a = *(const float4*)(A + (size_t)(rowBase + arow) * Hh + k0 + acol);
        As[acol+0][arow] = a.x; As[acol+1][arow] = a.y;
        As[acol+2][arow] = a.z; As[acol+3][arow] = a.w;
        *(float4*)&Bs[brow][bcol] =
            *(const float4*)(wo + (size_t)(k0 + brow) * Hh + colBase + bcol);
        __syncthreads();
        #pragma unroll
        for (int kk = 0; kk < BK; kk++) {
            float4 av = *(float4*)&As[kk][ty * 4];
            float4 bv = *(float4*)&Bs[kk][tx * 4];
            float ar[4] = {av.x, av.y, av.z, av.w};
            float br[4] = {bv.x, bv.y, bv.z, bv.w};
            #pragma unroll
            for (int i = 0; i < 4; i++)
                #pragma unroll
                for (int j = 0; j < 4; j++) acc[i][j] += ar[i] * br[j];
        }
        __syncthreads();
    }
    #pragma unroll
    for (int i = 0; i < 4; i++) {
        size_t ro = (size_t)(rowBase + ty * 4 + i) * Hh + colBase + tx * 4;
        float4 xv = *(const float4*)(x + ro);
        float4 o = make_float4(acc[i][0] + xv.x, acc[i][1] + xv.y,
                               acc[i][2] + xv.z, acc[i][3] + xv.w);
        *(float4*)(g_h + ro) = o;
    }
}

// ---------------- attention: one warp per (b, head, query row) ----------------
__device__ __forceinline__ void attn_update(float s, float vx, float vy,
                                            float& m, float& l, float& ax, float& ay) {
    float mn = fmaxf(m, s);
    float sc = __expf(m - mn);
    float p  = __expf(s - mn);
    l  = l * sc + p;
    ax = ax * sc + p * vx;
    ay = ay * sc + p * vy;
    m  = mn;
}

__global__ void k_attn() {
    int gw   = (blockIdx.x * blockDim.x + threadIdx.x) >> 5;
    int lane = threadIdx.x & 31;
    if (gw >= Bb * NHh * Ss) return;
    int qi   = gw & (Ss - 1);
    int bh   = gw >> 10;
    int head = bh & (NHh - 1);
    int b    = bh >> 4;
    float2 qv = *(const float2*)(g_q + (size_t)(b * Ss + qi) * Hh + head * HDd + 2 * lane);
    qv.x *= 0.125f; qv.y *= 0.125f;          // 1/sqrt(64)
    const float* kb = g_k + ((size_t)b * Ss * Hh + head * HDd + 2 * lane);
    const float* vb = g_v + ((size_t)b * Ss * Hh + head * HDd + 2 * lane);
    float m = -1e30f, l = 0.f, ax = 0.f, ay = 0.f;
    int nk = qi + 1;
    int j = 0;
    for (; j + 4 <= nk; j += 4) {
        float2 k0 = *(const float2*)(kb + (size_t)(j + 0) * Hh);
        float2 k1 = *(const float2*)(kb + (size_t)(j + 1) * Hh);
        float2 k2 = *(const float2*)(kb + (size_t)(j + 2) * Hh);
        float2 k3 = *(const float2*)(kb + (size_t)(j + 3) * Hh);
        float s0 = qv.x * k0.x + qv.y * k0.y;
        float s1 = qv.x * k1.x + qv.y * k1.y;
        float s2 = qv.x * k2.x + qv.y * k2.y;
        float s3 = qv.x * k3.x + qv.y * k3.y;
        #pragma unroll
        for (int o = 16; o > 0; o >>= 1) {
            s0 += __shfl_xor_sync(0xffffffffu, s0, o);
            s1 += __shfl_xor_sync(0xffffffffu, s1, o);
            s2 += __shfl_xor_sync(0xffffffffu, s2, o);
            s3 += __shfl_xor_sync(0xffffffffu, s3, o);
        }
        float2 v0 = *(const float2*)(vb + (size_t)(j + 0) * Hh);
        float2 v1 = *(const float2*)(vb + (size_t)(j + 1) * Hh);
        float2 v2 = *(const float2*)(vb + (size_t)(j + 2) * Hh);
        float2 v3 = *(const float2*)(vb + (size_t)(j + 3) * Hh);
        attn_update(s0, v0.x, v0.y, m, l, ax, ay);
        attn_update(s1, v1.x, v1.y, m, l, ax, ay);
        attn_update(s2, v2.x, v2.y, m, l, ax, ay);
        attn_update(s3, v3.x, v3.y, m, l, ax, ay);
    }
    for (; j < nk; j++) {
        float2 kvv = *(const float2*)(kb + (size_t)j * Hh);
        float s = qv.x * kvv.x + qv.y * kvv.y;
        #pragma unroll
        for (int o = 16; o > 0; o >>= 1) s += __shfl_xor_sync(0xffffffffu, s, o);
        float2 vv = *(const float2*)(vb + (size_t)j * Hh);
        attn_update(s, vv.x, vv.y, m, l, ax, ay);
    }
    float inv = 1.f / l;
    float2 o = make_float2(ax * inv, ay * inv);
    *(float2*)(g_ao + (size_t)(b * Ss + qi) * Hh + head * HDd + 2 * lane) = o;
}

// ---------------- router: one warp per token ----------------
__global__ void k_router(const float* __restrict__ rw) {
    int t    = (blockIdx.x * blockDim.x + threadIdx.x) >> 5;
    int lane = threadIdx.x & 31;
    if (t >= Tt) return;
    const float* xr = g_hn + (size_t)t * Hh;
    float acc[Ee] = {};
    for (int hh = lane; hh < Hh; hh += 32) {
        float xv = xr[hh];
        #pragma unroll
        for (int e = 0; e < Ee; e++) acc[e] += xv * rw[hh * Ee + e];
    }
    #pragma unroll
    for (int e = 0; e < Ee; e++)
        #pragma unroll
        for (int o = 16; o > 0; o >>= 1) acc[e] += __shfl_xor_sync(0xffffffffu, acc[e], o);
    if (lane == 0) {
        float mx = acc[0];
        #pragma unroll
        for (int e = 1; e < Ee; e++) mx = fmaxf(mx, acc[e]);
        float p[Ee], s = 0.f;
        #pragma unroll
        for (int e = 0; e < Ee; e++) { p[e] = __expf(acc[e] - mx); s += p[e]; }
        float invs = 1.f / s;
        #pragma unroll
        for (int e = 0; e < Ee; e++) p[e] *= invs;
        int i1 = 0; float v1 = p[0];
        #pragma unroll
        for (int e = 1; e < Ee; e++) if (p[e] > v1) { v1 = p[e]; i1 = e; }
        int i2 = -1; float v2 = -1.f;
        #pragma unroll
        for (int e = 0; e < Ee; e++) if (e != i1 && p[e] > v2) { v2 = p[e]; i2 = e; }
        float inv = 1.f / (v1 + v2);
        g_topi[t * 2]     = i1; g_topi[t * 2 + 1] = i2;
        g_topw[t * 2]     = v1 * inv; g_topw[t * 2 + 1] = v2 * inv;
        atomicAdd(&g_cnt[i1], 1); atomicAdd(&g_cnt[i2], 1);
    }
}

__global__ void k_scan() {
    if (threadIdx.x == 0) {
        int o = 0;
        for (int e = 0; e < Ee; e++) { g_off[e] = o; o += g_cnt[e]; g_fill[e] = 0; }
    }
}

__global__ void k_fill() {
    int t = blockIdx.x * blockDim.x + threadIdx.x;
    if (t >= Tt) return;
    for (int kk = 0; kk < 2; kk++) {
        int e = g_topi[t * 2 + kk];
        int pos = atomicAdd(&g_fill[e], 1);
        int slot = g_off[e] + pos;
        g_tok[slot] = t;
        g_slot[t * 2 + kk] = slot;
    }
}

// ---------------- MoE GEMM 1: act = silu(hn@w1) * (hn@w3), gathered rows ----------------
__global__ void k_moe1(const float* __restrict__ w1, const float* __restrict__ w3) {
    int e = blockIdx.z;
    int cnt = g_cnt[e], base = g_off[e];
    int rtile = blockIdx.y * BM;
    if (rtile >= cnt) return;
    const float* B1 = w1 + (size_t)e * Hh * Ii;
    const float* B3 = w3 + (size_t)e * Hh * Ii;
    __shared__ float As[BK][BM];
    __shared__ float Bs1[BK][BN];
    __shared__ float Bs3[BK][BN];
    int tx = threadIdx.x, ty = threadIdx.y;
    int tid = ty * 16 + tx;
    int arow = tid >> 2, acol = (tid & 3) * 4;
    int brow = tid >> 4, bcol = (tid & 15) * 4;
    int colBase = blockIdx.x * BN;
    bool validA = (rtile + arow) < cnt;
    int tok = validA ? g_tok[base + rtile + arow] : g_tok[base];
    const float* Aptr = g_hn + (size_t)tok * Hh;
    float acc1[4][4] = {}, acc3[4][4] = {};
    for (int k0 = 0; k0 < Hh; k0 += BK) {
        float4 a = *(const float4*)(Aptr + k0 + acol);
        As[acol+0][arow] = a.x; As[acol+1][arow] = a.y;
        As[acol+2][arow] = a.z; As[acol+3][arow] = a.w;
        *(float4*)&Bs1[brow][bcol] =
            *(const float4*)(B1 + (size_t)(k0 + brow) * Ii + colBase + bcol);
        *(float4*)&Bs3[brow][bcol] =
            *(const float4*)(B3 + (size_t)(k0 + brow) * Ii + colBase + bcol);
        __syncthreads();
        #pragma unroll
        for (int kk = 0; kk < BK; kk++) {
            float4 av = *(float4*)&As[kk][ty * 4];
            float4 b1v = *(float4*)&Bs1[kk][tx * 4];
            float4 b3v = *(float4*)&Bs3[kk][tx * 4];
            float ar[4] = {av.x, av.y, av.z, av.w};
            float b1r[4] = {b1v.x, b1v.y, b1v.z, b1v.w};
            float b3r[4] = {b3v.x, b3v.y, b3v.z, b3v.w};
            #pragma unroll
            for (int i = 0; i < 4; i++)
                #pragma unroll
                for (int j = 0; j < 4; j++) {
                    acc1[i][j] += ar[i] * b1r[j];
                    acc3[i][j] += ar[i] * b3r[j];
                }
        }
        __syncthreads();
    }
    #pragma unroll
    for (int i = 0; i < 4; i++) {
        int rloc = rtile + ty * 4 + i;
        if (rloc >= cnt) continue;
        float4 o;
        float* op = &o.x;
        #pragma unroll
        for (int j = 0; j < 4; j++) {
            float h1 = acc1[i][j], h3 = acc3[i][j];
            op[j] = (h1 / (1.f + __expf(-h1))) * h3;
        }
        *(float4*)(g_act + (size_t)(base + rloc) * Ii + colBase + tx * 4) = o;
    }
}

// ---------------- MoE GEMM 2: y = act @ w2[e] ----------------
__global__ void k_moe2(const float* __restrict__ w2) {
    int e = blockIdx.z;
    int cnt = g_cnt[e], base = g_off[e];
    int rtile = blockIdx.y * BM;
    if (rtile >= cnt) return;
    const float* Bm = w2 + (size_t)e * Ii * Hh;
    __shared__ float As[BK][BM];
    __shared__ float Bs[BK][BN];
    int tx = threadIdx.x, ty = threadIdx.y;
    int tid = ty * 16 + tx;
    int arow = tid >> 2, acol = (tid & 3) * 4;
    int brow = tid >> 4, bcol = (tid & 15) * 4;
    int colBase = blockIdx.x * BN;
    bool validA = (rtile + arow) < cnt;
    int rowIdx = validA ? (base + rtile + arow) : base;
    const float* Aptr = g_act + (size_t)rowIdx * Ii;
    float acc[4][4] = {};
    for (int k0 = 0; k0 < Ii; k0 += BK) {
        float4 a = *(const float4*)(Aptr + k0 + acol);
        As[acol+0][arow] = a.x; As[acol+1][arow] = a.y;
        As[acol+2][arow] = a.z; As[acol+3][arow] = a.w;
        *(float4*)&Bs[brow][bcol] =
            *(const float4*)(Bm + (size_t)(k0 + brow) * Hh + colBase + bcol);
        __syncthreads();
        #pragma unroll
        for (int kk = 0; kk < BK; kk++) {
            float4 av = *(float4*)&As[kk][ty * 4];
            float4 bv = *(float4*)&Bs[kk][tx * 4];
            float ar[4] = {av.x, av.y, av.z, av.w};
            float br[4] = {bv.x, bv.y, bv.z, bv.w};
            #pragma unroll
            for (int i = 0; i < 4; i++)
                #pragma unroll
                for (int j = 0; j < 4; j++) acc[i][j] += ar[i] * br[j];
        }
        __syncthreads();
    }
    #pragma unroll
    for (int i = 0; i < 4; i++) {
        int rloc = rtile + ty * 4 + i;
        if (rloc >= cnt) continue;
        float4 o = make_float4(acc[i][0], acc[i][1], acc[i][2], acc[i][3]);
        *(float4*)(g_y + (size_t)(base + rloc) * Hh + colBase + tx * 4) = o;
    }
}

// ---------------- combine: out = h + w0*y[slot0] + w1*y[slot1] ----------------
__global__ void k_combine(float* __restrict__ out) {
    int t = blockIdx.x;
    int i = threadIdx.x;                 // 256 threads * float4 = 1024
    int s0 = g_slot[t * 2], s1 = g_slot[t * 2 + 1];
    float w0 = g_topw[t * 2], w1 = g_topw[t * 2 + 1];
    float4 hv = ((const float4*)g_h)[(size_t)t * 256 + i];
    float4 y0 = ((const float4*)g_y)[(size_t)s0 * 256 + i];
    float4 y1 = ((const float4*)g_y)[(size_t)s1 * 256 + i];
    float4 o;
    o.x = hv.x + w0 * y0.x + w1 * y1.x;
    o.y = hv.y + w0 * y0.y + w1 * y1.y;
    o.z = hv.z + w0 * y0.z + w1 * y1.z;
    o.w = hv.w + w0 * y0.w + w1 * y1.w;
    ((float4*)out)[(size_t)t * 256 + i] = o;
}

// ---------------- launch ----------------
extern "C" void kernel_launch(void* const* d_in, const int* in_sizes, int n_in,
                              void* d_out, int out_size) {
    const float* x    = (const float*)d_in[0];
    const float* anw  = (const float*)d_in[1];
    const float* fnw  = (const float*)d_in[2];
    const float* wq   = (const float*)d_in[3];
    const float* wk   = (const float*)d_in[4];
    const float* wv   = (const float*)d_in[5];
    const float* wo   = (const float*)d_in[6];
    const float* rw   = (const float*)d_in[7];
    const float* w1   = (const float*)d_in[8];
    const float* w3   = (const float*)d_in[9];
    const float* w2   = (const float*)d_in[10];
    const float* fc   = (const float*)d_in[11];
    float* out = (float*)d_out;

    float* d_xn; cudaGetSymbolAddress((void**)&d_xn, g_xn);
    float* d_h;  cudaGetSymbolAddress((void**)&d_h,  g_h);
    float* d_hn; cudaGetSymbolAddress((void**)&d_hn, g_hn);

    dim3 tb(16, 16);

    k_zero<<<1, 32>>>();
    k_rmsnorm<<<Tt, 256>>>(x, anw, d_xn);
    k_qkv<<<dim3(Hh / BN, Tt / BM, 3), tb>>>(wq, wk, wv);
    k_rope<<<dim3((Tt * NHh * 32) / 256, 2), 256>>>(fc);
    k_attn<<<(Bb * NHh * Ss) / 4, 128>>>();
    k_wo<<<dim3(Hh / BN, Tt / BM), tb>>>(wo, x);
    k_rmsnorm<<<Tt, 256>>>(d_h, fnw, d_hn);
    k_router<<<Tt / 8, 256>>>(rw);
    k_scan<<<1, 32>>>();
    k_fill<<<Tt / 256, 256>>>();
    k_moe1<<<dim3(Ii / BN, Tt / BM, Ee), tb>>>(w1, w3);
    k_moe2<<<dim3(Hh / BN, Tt / BM, Ee), tb>>>(w2);
    k_combine<<<Tt, 256>>>(out);
}

// round 3
// speedup vs baseline: 1.0021x; 1.0021x over previous
#include <cuda_runtime.h>
#include <math.h>

// ---- problem dims (fixed) ----
#define Bb   2
#define Ss   1024
#define Tt   2048          // B*S tokens
#define Hh   1024
#define NHh  16
#define HDd  64
#define Ee   8
#define Ii   2048
#define NSLOT (Tt*2)       // total (token, expert) pairs = 4096

// ---- scratch (device globals; no allocations allowed) ----
__device__ float g_xn[Tt*Hh];
__device__ float g_q [Tt*Hh];
__device__ float g_k [Tt*Hh];
__device__ float g_v [Tt*Hh];
__device__ float g_ao[Tt*Hh];    // attention output (pre-WO)
__device__ float g_h [Tt*Hh];    // residual after attention
__device__ float g_hn[Tt*Hh];    // ffn-normed
__device__ float g_act[NSLOT*Ii];  // swiglu activations per slot
__device__ float g_y  [NSLOT*Hh];  // expert outputs per slot
__device__ int   g_topi[Tt*2];
__device__ float g_topw[Tt*2];
__device__ int   g_slot[Tt*2];
__device__ int   g_tok [NSLOT];
__device__ int   g_cnt [Ee];
__device__ int   g_off [Ee];
__device__ int   g_fill[Ee];

// ---------------- elementwise / small kernels ----------------

__global__ void k_zero() {
    int i = threadIdx.x;
    if (i < Ee) { g_cnt[i] = 0; g_fill[i] = 0; }
}

// one block (256 thr) per token row; each thread one float4
__global__ void k_rmsnorm(const float* __restrict__ x, const float* __restrict__ w,
                          float* __restrict__ out) {
    int t = blockIdx.x;
    int i = threadIdx.x;
    const float4* xr = (const float4*)(x + (size_t)t * Hh);
    float4 v = xr[i];
    float ss = v.x*v.x + v.y*v.y + v.z*v.z + v.w*v.w;
    __shared__ float red[256];
    red[i] = ss; __syncthreads();
    for (int s = 128; s > 0; s >>= 1) {
        if (i < s) red[i] += red[i + s];
        __syncthreads();
    }
    float rinv = rsqrtf(red[0] * (1.0f / Hh) + 1e-6f);
    float4 wv = ((const float4*)w)[i];
    float4 o;
    o.x = v.x * rinv * wv.x; o.y = v.y * rinv * wv.y;
    o.z = v.z * rinv * wv.z; o.w = v.w * rinv * wv.w;
    ((float4*)(out + (size_t)t * Hh))[i] = o;
}

// RoPE in place on q and k (gridDim.y selects tensor)
__global__ void k_rope(const float* __restrict__ fc) {
    int idx = blockIdx.x * blockDim.x + threadIdx.x;   // pair index
    float* X = (blockIdx.y == 0) ? g_q : g_k;
    int j    = idx & 31;
    int head = (idx >> 5) & (NHh - 1);
    int t    = idx >> 9;
    if (t >= Tt) return;
    int s = t & (Ss - 1);
    float2* p = (float2*)(X + (size_t)t * Hh + head * HDd + 2 * j);
    float2 ab = *p;
    float cr = fc[s * HDd + 2 * j];
    float ci = fc[s * HDd + 2 * j + 1];
    float2 o;
    o.x = ab.x * cr - ab.y * ci;
    o.y = ab.x * ci + ab.y * cr;
    *p = o;
}

// ---------------- SGEMM core (64x64x16 tiles, 256 thr, 4x4/thr) ----------------
#define BM 64
#define BN 64
#define BK 16

// QKV: C = xn @ {wq,wk,wv} selected by blockIdx.z
__global__ void k_qkv(const float* __restrict__ wq, const float* __restrict__ wk,
                      const float* __restrict__ wv) {
    const float* Bm = (blockIdx.z == 0) ? wq : (blockIdx.z == 1) ? wk : wv;
    float* C = (blockIdx.z == 0) ? g_q : (blockIdx.z == 1) ? g_k : g_v;
    const float* A = g_xn;
    __shared__ float As[BK][BM];
    __shared__ float Bs[BK][BN];
    int tx = threadIdx.x, ty = threadIdx.y;
    int tid = ty * 16 + tx;
    int arow = tid >> 2, acol = (tid & 3) * 4;
    int brow = tid >> 4, bcol = (tid & 15) * 4;
    int rowBase = blockIdx.y * BM, colBase = blockIdx.x * BN;
    float acc[4][4] = {};
    for (int k0 = 0; k0 < Hh; k0 += BK) {
        float4 a = *(const float4*)(A + (size_t)(rowBase + arow) * Hh + k0 + acol);
        As[acol+0][arow] = a.x; As[acol+1][arow] = a.y;
        As[acol+2][arow] = a.z; As[acol+3][arow] = a.w;
        *(float4*)&Bs[brow][bcol] =
            *(const float4*)(Bm + (size_t)(k0 + brow) * Hh + colBase + bcol);
        __syncthreads();
        #pragma unroll
        for (int kk = 0; kk < BK; kk++) {
            float4 av = *(float4*)&As[kk][ty * 4];
            float4 bv = *(float4*)&Bs[kk][tx * 4];
            float ar[4] = {av.x, av.y, av.z, av.w};
            float br[4] = {bv.x, bv.y, bv.z, bv.w};
            #pragma unroll
            for (int i = 0; i < 4; i++)
                #pragma unroll
                for (int j = 0; j < 4; j++) acc[i][j] += ar[i] * br[j];
        }
        __syncthreads();
    }
    #pragma unroll
    for (int i = 0; i < 4; i++) {
        float4 o = make_float4(acc[i][0], acc[i][1], acc[i][2], acc[i][3]);
        *(float4*)(C + (size_t)(rowBase + ty * 4 + i) * Hh + colBase + tx * 4) = o;
    }
}

// WO with residual: h = x + ao @ wo
__global__ void k_wo(const float* __restrict__ wo, const float* __restrict__ x) {
    const float* A = g_ao;
    __shared__ float As[BK][BM];
    __shared__ float Bs[BK][BN];
    int tx = threadIdx.x, ty = threadIdx.y;
    int tid = ty * 16 + tx;
    int arow = tid >> 2, acol = (tid & 3) * 4;
    int brow = tid >> 4, bcol = (tid & 15) * 4;
    int rowBase = blockIdx.y * BM, colBase = blockIdx.x * BN;
    float acc[4][4] = {};
    for (int k0 = 0; k0 < Hh; k0 += BK) {
        float4 a = *(const float4*)(A + (size_t)(rowBase + arow) * Hh + k0 + acol);
        As[acol+0][arow] = a.x; As[acol+1][arow] = a.y;
        As[acol+2][arow] = a.z; As[acol+3][arow] = a.w;
        *(float4*)&Bs[brow][bcol] =
            *(const float4*)(wo + (size_t)(k0 + brow) * Hh + colBase + bcol);
        __syncthreads();
        #pragma unroll
        for (int kk = 0; kk < BK; kk++) {
            float4 av = *(float4*)&As[kk][ty * 4];
            float4 bv = *(float4*)&Bs[kk][tx * 4];
            float ar[4] = {av.x, av.y, av.z, av.w};
            float br[4] = {bv.x, bv.y, bv.z, bv.w};
            #pragma unroll
            for (int i = 0; i < 4; i++)
                #pragma unroll
                for (int j = 0; j < 4; j++) acc[i][j] += ar[i] * br[j];
        }
        __syncthreads();
    }
    #pragma unroll
    for (int i = 0; i < 4; i++) {
        size_t ro = (size_t)(rowBase + ty * 4 + i) * Hh + colBase + tx * 4;
        float4 xv = *(const float4*)(x + ro);
        float4 o = make_float4(acc[i][0] + xv.x, acc[i][1] + xv.y,
                               acc[i][2] + xv.z, acc[i][3] + xv.w);
        *(float4*)(g_h + ro) = o;
    }
}

// ---------------- attention: one warp per (b, head, query row) ----------------
__device__ __forceinline__ void attn_update(float s, float vx, float vy,
                                            float& m, float& l, float& ax, float& ay) {
    float mn = fmaxf(m, s);
    float sc = __expf(m - mn);
    float p  = __expf(s - mn);
    l  = l * sc + p;
    ax = ax * sc + p * vx;
    ay = ay * sc + p * vy;
    m  = mn;
}

__global__ void k_attn() {
    int gw   = (blockIdx.x * blockDim.x + threadIdx.x) >> 5;
    int lane = threadIdx.x & 31;
    if (gw >= Bb * NHh * Ss) return;
    int qi   = gw & (Ss - 1);
    int bh   = gw >> 10;
    int head = bh & (NHh - 1);
    int b    = bh >> 4;
    float2 qv = *(const float2*)(g_q + (size_t)(b * Ss + qi) * Hh + head * HDd + 2 * lane);
    qv.x *= 0.125f; qv.y *= 0.125f;          // 1/sqrt(64)
    const float* kb = g_k + ((size_t)b * Ss * Hh + head * HDd + 2 * lane);
    const float* vb = g_v + ((size_t)b * Ss * Hh + head * HDd + 2 * lane);
    float m = -1e30f, l = 0.f, ax = 0.f, ay = 0.f;
    int nk = qi + 1;
    int j = 0;
    for (; j + 4 <= nk; j += 4) {
        float2 k0 = *(const float2*)(kb + (size_t)(j + 0) * Hh);
        float2 k1 = *(const float2*)(kb + (size_t)(j + 1) * Hh);
        float2 k2 = *(const float2*)(kb + (size_t)(j + 2) * Hh);
        float2 k3 = *(const float2*)(kb + (size_t)(j + 3) * Hh);
        float s0 = qv.x * k0.x + qv.y * k0.y;
        float s1 = qv.x * k1.x + qv.y * k1.y;
        float s2 = qv.x * k2.x + qv.y * k2.y;
        float s3 = qv.x * k3.x + qv.y * k3.y;
        #pragma unroll
        for (int o = 16; o > 0; o >>= 1) {
            s0 += __shfl_xor_sync(0xffffffffu, s0, o);
            s1 += __shfl_xor_sync(0xffffffffu, s1, o);
            s2 += __shfl_xor_sync(0xffffffffu, s2, o);
            s3 += __shfl_xor_sync(0xffffffffu, s3, o);
        }
        float2 v0 = *(const float2*)(vb + (size_t)(j + 0) * Hh);
        float2 v1 = *(const float2*)(vb + (size_t)(j + 1) * Hh);
        float2 v2 = *(const float2*)(vb + (size_t)(j + 2) * Hh);
        float2 v3 = *(const float2*)(vb + (size_t)(j + 3) * Hh);
        attn_update(s0, v0.x, v0.y, m, l, ax, ay);
        attn_update(s1, v1.x, v1.y, m, l, ax, ay);
        attn_update(s2, v2.x, v2.y, m, l, ax, ay);
        attn_update(s3, v3.x, v3.y, m, l, ax, ay);
    }
    for (; j < nk; j++) {
        float2 kvv = *(const float2*)(kb + (size_t)j * Hh);
        float s = qv.x * kvv.x + qv.y * kvv.y;
        #pragma unroll
        for (int o = 16; o > 0; o >>= 1) s += __shfl_xor_sync(0xffffffffu, s, o);
        float2 vv = *(const float2*)(vb + (size_t)j * Hh);
        attn_update(s, vv.x, vv.y, m, l, ax, ay);
    }
    float inv = 1.f / l;
    float2 o = make_float2(ax * inv, ay * inv);
    *(float2*)(g_ao + (size_t)(b * Ss + qi) * Hh + head * HDd + 2 * lane) = o;
}

// ---------------- router: one warp per token ----------------
__global__ void k_router(const float* __restrict__ rw) {
    int t    = (blockIdx.x * blockDim.x + threadIdx.x) >> 5;
    int lane = threadIdx.x & 31;
    if (t >= Tt) return;
    const float* xr = g_hn + (size_t)t * Hh;
    float acc[Ee] = {};
    for (int hh = lane; hh < Hh; hh += 32) {
        float xv = xr[hh];
        #pragma unroll
        for (int e = 0; e < Ee; e++) acc[e] += xv * rw[hh * Ee + e];
    }
    #pragma unroll
    for (int e = 0; e < Ee; e++)
        #pragma unroll
        for (int o = 16; o > 0; o >>= 1) acc[e] += __shfl_xor_sync(0xffffffffu, acc[e], o);
    if (lane == 0) {
        float mx = acc[0];
        #pragma unroll
        for (int e = 1; e < Ee; e++) mx = fmaxf(mx, acc[e]);
        float p[Ee], s = 0.f;
        #pragma unroll
        for (int e = 0; e < Ee; e++) { p[e] = __expf(acc[e] - mx); s += p[e]; }
        float invs = 1.f / s;
        #pragma unroll
        for (int e = 0; e < Ee; e++) p[e] *= invs;
        int i1 = 0; float v1 = p[0];
        #pragma unroll
        for (int e = 1; e < Ee; e++) if (p[e] > v1) { v1 = p[e]; i1 = e; }
        int i2 = -1; float v2 = -1.f;
        #pragma unroll
        for (int e = 0; e < Ee; e++) if (e != i1 && p[e] > v2) { v2 = p[e]; i2 = e; }
        float inv = 1.f / (v1 + v2);
        g_topi[t * 2]     = i1; g_topi[t * 2 + 1] = i2;
        g_topw[t * 2]     = v1 * inv; g_topw[t * 2 + 1] = v2 * inv;
        atomicAdd(&g_cnt[i1], 1); atomicAdd(&g_cnt[i2], 1);
    }
}

__global__ void k_scan() {
    if (threadIdx.x == 0) {
        int o = 0;
        for (int e = 0; e < Ee; e++) { g_off[e] = o; o += g_cnt[e]; g_fill[e] = 0; }
    }
}

__global__ void k_fill() {
    int t = blockIdx.x * blockDim.x + threadIdx.x;
    if (t >= Tt) return;
    for (int kk = 0; kk < 2; kk++) {
        int e = g_topi[t * 2 + kk];
        int pos = atomicAdd(&g_fill[e], 1);
        int slot = g_off[e] + pos;
        g_tok[slot] = t;
        g_slot[t * 2 + kk] = slot;
    }
}

// ---------------- MoE GEMM 1: act = silu(hn@w1) * (hn@w3), gathered rows ----------------
__global__ void k_moe1(const float* __restrict__ w1, const float* __restrict__ w3) {
    int e = blockIdx.z;
    int cnt = g_cnt[e], base = g_off[e];
    int rtile = blockIdx.y * BM;
    if (rtile >= cnt) return;
    const float* B1 = w1 + (size_t)e * Hh * Ii;
    const float* B3 = w3 + (size_t)e * Hh * Ii;
    __shared__ float As[BK][BM];
    __shared__ float Bs1[BK][BN];
    __shared__ float Bs3[BK][BN];
    int tx = threadIdx.x, ty = threadIdx.y;
    int tid = ty * 16 + tx;
    int arow = tid >> 2, acol = (tid & 3) * 4;
    int brow = tid >> 4, bcol = (tid & 15) * 4;
    int colBase = blockIdx.x * BN;
    bool validA = (rtile + arow) < cnt;
    int tok = validA ? g_tok[base + rtile + arow] : g_tok[base];
    const float* Aptr = g_hn + (size_t)tok * Hh;
    float acc1[4][4] = {}, acc3[4][4] = {};
    for (int k0 = 0; k0 < Hh; k0 += BK) {
        float4 a = *(const float4*)(Aptr + k0 + acol);
        As[acol+0][arow] = a.x; As[acol+1][arow] = a.y;
        As[acol+2][arow] = a.z; As[acol+3][arow] = a.w;
        *(float4*)&Bs1[brow][bcol] =
            *(const float4*)(B1 + (size_t)(k0 + brow) * Ii + colBase + bcol);
        *(float4*)&Bs3[brow][bcol] =
            *(const float4*)(B3 + (size_t)(k0 + brow) * Ii + colBase + bcol);
        __syncthreads();
        #pragma unroll
        for (int kk = 0; kk < BK; kk++) {
            float4 av = *(float4*)&As[kk][ty * 4];
            float4 b1v = *(float4*)&Bs1[kk][tx * 4];
            float4 b3v = *(float4*)&Bs3[kk][tx * 4];
            float ar[4] = {av.x, av.y, av.z, av.w};
            float b1r[4] = {b1v.x, b1v.y, b1v.z, b1v.w};
            float b3r[4] = {b3v.x, b3v.y, b3v.z, b3v.w};
            #pragma unroll
            for (int i = 0; i < 4; i++)
                #pragma unroll
                for (int j = 0; j < 4; j++) {
                    acc1[i][j] += ar[i] * b1r[j];
                    acc3[i][j] += ar[i] * b3r[j];
                }
        }
        __syncthreads();
    }
    #pragma unroll
    for (int i = 0; i < 4; i++) {
        int rloc = rtile + ty * 4 + i;
        if (rloc >= cnt) continue;
        float4 o;
        float* op = &o.x;
        #pragma unroll
        for (int j = 0; j < 4; j++) {
            float h1 = acc1[i][j], h3 = acc3[i][j];
            op[j] = (h1 / (1.f + __expf(-h1))) * h3;
        }
        *(float4*)(g_act + (size_t)(base + rloc) * Ii + colBase + tx * 4) = o;
    }
}

// ---------------- MoE GEMM 2: y = act @ w2[e] ----------------
__global__ void k_moe2(const float* __restrict__ w2) {
    int e = blockIdx.z;
    int cnt = g_cnt[e], base = g_off[e];
    int rtile = blockIdx.y * BM;
    if (rtile >= cnt) return;
    const float* Bm = w2 + (size_t)e * Ii * Hh;
    __shared__ float As[BK][BM];
    __shared__ float Bs[BK][BN];
    int tx = threadIdx.x, ty = threadIdx.y;
    int tid = ty * 16 + tx;
    int arow = tid >> 2, acol = (tid & 3) * 4;
    int brow = tid >> 4, bcol = (tid & 15) * 4;
    int colBase = blockIdx.x * BN;
    bool validA = (rtile + arow) < cnt;
    int rowIdx = validA ? (base + rtile + arow) : base;
    const float* Aptr = g_act + (size_t)rowIdx * Ii;
    float acc[4][4] = {};
    for (int k0 = 0; k0 < Ii; k0 += BK) {
        float4 a = *(const float4*)(Aptr + k0 + acol);
        As[acol+0][arow] = a.x; As[acol+1][arow] = a.y;
        As[acol+2][arow] = a.z; As[acol+3][arow] = a.w;
        *(float4*)&Bs[brow][bcol] =
            *(const float4*)(Bm + (size_t)(k0 + brow) * Hh + colBase + bcol);
        __syncthreads();
        #pragma unroll
        for (int kk = 0; kk < BK; kk++) {
            float4 av = *(float4*)&As[kk][ty * 4];
            float4 bv = *(float4*)&Bs[kk][tx * 4];
            float ar[4] = {av.x, av.y, av.z, av.w};
            float br[4] = {bv.x, bv.y, bv.z, bv.w};
            #pragma unroll
            for (int i = 0; i < 4; i++)
                #pragma unroll
                for (int j = 0; j < 4; j++) acc[i][j] += ar[i] * br[j];
        }
        __syncthreads();
    }
    #pragma unroll
    for (int i = 0; i < 4; i++) {
        int rloc = rtile + ty * 4 + i;
        if (rloc >= cnt) continue;
        float4 o = make_float4(acc[i][0], acc[i][1], acc[i][2], acc[i][3]);
        *(float4*)(g_y + (size_t)(base + rloc) * Hh + colBase + tx * 4) = o;
    }
}

// ---------------- combine: out = h + w0*y[slot0] + w1*y[slot1] ----------------
__global__ void k_combine(float* __restrict__ out) {
    int t = blockIdx.x;
    int i = threadIdx.x;                 // 256 threads * float4 = 1024
    int s0 = g_slot[t * 2], s1 = g_slot[t * 2 + 1];
    float w0 = g_topw[t * 2], w1 = g_topw[t * 2 + 1];
    float4 hv = ((const float4*)g_h)[(size_t)t * 256 + i];
    float4 y0 = ((const float4*)g_y)[(size_t)s0 * 256 + i];
    float4 y1 = ((const float4*)g_y)[(size_t)s1 * 256 + i];
    float4 o;
    o.x = hv.x + w0 * y0.x + w1 * y1.x;
    o.y = hv.y + w0 * y0.y + w1 * y1.y;
    o.z = hv.z + w0 * y0.z + w1 * y1.z;
    o.w = hv.w + w0 * y0.w + w1 * y1.w;
    ((float4*)out)[(size_t)t * 256 + i] = o;
}

// ---------------- launch ----------------
extern "C" void kernel_launch(void* const* d_in, const int* in_sizes, int n_in,
                              void* d_out, int out_size) {
    const float* x    = (const float*)d_in[0];
    const float* anw  = (const float*)d_in[1];
    const float* fnw  = (const float*)d_in[2];
    const float* wq   = (const float*)d_in[3];
    const float* wk   = (const float*)d_in[4];
    const float* wv   = (const float*)d_in[5];
    const float* wo   = (const float*)d_in[6];
    const float* rw   = (const float*)d_in[7];
    const float* w1   = (const float*)d_in[8];
    const float* w3   = (const float*)d_in[9];
    const float* w2   = (const float*)d_in[10];
    const float* fc   = (const float*)d_in[11];
    float* out = (float*)d_out;

    float* d_xn; cudaGetSymbolAddress((void**)&d_xn, g_xn);
    float* d_h;  cudaGetSymbolAddress((void**)&d_h,  g_h);
    float* d_hn; cudaGetSymbolAddress((void**)&d_hn, g_hn);

    dim3 tb(16, 16);

    k_zero<<<1, 32>>>();
    k_rmsnorm<<<Tt, 256>>>(x, anw, d_xn);
    k_qkv<<<dim3(Hh / BN, Tt / BM, 3), tb>>>(wq, wk, wv);
    k_rope<<<dim3((Tt * NHh * 32) / 256, 2), 256>>>(fc);
    k_attn<<<(Bb * NHh * Ss) / 4, 128>>>();
    k_wo<<<dim3(Hh / BN, Tt / BM), tb>>>(wo, x);
    k_rmsnorm<<<Tt, 256>>>(d_h, fnw, d_hn);
    k_router<<<Tt / 8, 256>>>(rw);
    k_scan<<<1, 32>>>();
    k_fill<<<Tt / 256, 256>>>();
    k_moe1<<<dim3(Ii / BN, Tt / BM, Ee), tb>>>(w1, w3);
    k_moe2<<<dim3(Hh / BN, Tt / BM, Ee), tb>>>(w2);
    k_combine<<<Tt, 256>>>(out);
}

// round 4
// speedup vs baseline: 1.0036x; 1.0015x over previous
#include <cuda_runtime.h>
#include <math.h>

// ---- problem dims (fixed) ----
#define Bb   2
#define Ss   1024
#define Tt   2048          // B*S tokens
#define Hh   1024
#define NHh  16
#define HDd  64
#define Ee   8
#define Ii   2048
#define NSLOT (Tt*2)       // total (token, expert) pairs = 4096

// ---- scratch (device globals; no allocations allowed) ----
__device__ float g_xn[Tt*Hh];
__device__ float g_q [Tt*Hh];
__device__ float g_k [Tt*Hh];
__device__ float g_v [Tt*Hh];
__device__ float g_ao[Tt*Hh];    // attention output (pre-WO)
__device__ float g_h [Tt*Hh];    // residual after attention
__device__ float g_hn[Tt*Hh];    // ffn-normed
__device__ float g_act[NSLOT*Ii];  // swiglu activations per slot
__device__ float g_y  [NSLOT*Hh];  // expert outputs per slot
__device__ int   g_topi[Tt*2];
__device__ float g_topw[Tt*2];
__device__ int   g_slot[Tt*2];
__device__ int   g_tok [NSLOT];
__device__ int   g_cnt [Ee];
__device__ int   g_off [Ee];
__device__ int   g_fill[Ee];

// ---------------- elementwise / small kernels ----------------

__global__ void k_zero() {
    int i = threadIdx.x;
    if (i < Ee) { g_cnt[i] = 0; g_fill[i] = 0; }
}

// one block (256 thr) per token row; each thread one float4
__global__ void k_rmsnorm(const float* __restrict__ x, const float* __restrict__ w,
                          float* __restrict__ out) {
    int t = blockIdx.x;
    int i = threadIdx.x;
    const float4* xr = (const float4*)(x + (size_t)t * Hh);
    float4 v = xr[i];
    float ss = v.x*v.x + v.y*v.y + v.z*v.z + v.w*v.w;
    __shared__ float red[256];
    red[i] = ss; __syncthreads();
    for (int s = 128; s > 0; s >>= 1) {
        if (i < s) red[i] += red[i + s];
        __syncthreads();
    }
    float rinv = rsqrtf(red[0] * (1.0f / Hh) + 1e-6f);
    float4 wv = ((const float4*)w)[i];
    float4 o;
    o.x = v.x * rinv * wv.x; o.y = v.y * rinv * wv.y;
    o.z = v.z * rinv * wv.z; o.w = v.w * rinv * wv.w;
    ((float4*)(out + (size_t)t * Hh))[i] = o;
}

// RoPE in place on q and k (gridDim.y selects tensor)
__global__ void k_rope(const float* __restrict__ fc) {
    int idx = blockIdx.x * blockDim.x + threadIdx.x;   // pair index
    float* X = (blockIdx.y == 0) ? g_q : g_k;
    int j    = idx & 31;
    int head = (idx >> 5) & (NHh - 1);
    int t    = idx >> 9;
    if (t >= Tt) return;
    int s = t & (Ss - 1);
    float2* p = (float2*)(X + (size_t)t * Hh + head * HDd + 2 * j);
    float2 ab = *p;
    float cr = fc[s * HDd + 2 * j];
    float ci = fc[s * HDd + 2 * j + 1];
    float2 o;
    o.x = ab.x * cr - ab.y * ci;
    o.y = ab.x * ci + ab.y * cr;
    *p = o;
}

// ---------------- SGEMM core (64x64x16 tiles, 256 thr, 4x4/thr) ----------------
#define BM 64
#define BN 64
#define BK 16

// QKV: C = xn @ {wq,wk,wv} selected by blockIdx.z
__global__ void k_qkv(const float* __restrict__ wq, const float* __restrict__ wk,
                      const float* __restrict__ wv) {
    const float* Bm = (blockIdx.z == 0) ? wq : (blockIdx.z == 1) ? wk : wv;
    float* C = (blockIdx.z == 0) ? g_q : (blockIdx.z == 1) ? g_k : g_v;
    const float* A = g_xn;
    __shared__ float As[BK][BM];
    __shared__ float Bs[BK][BN];
    int tx = threadIdx.x, ty = threadIdx.y;
    int tid = ty * 16 + tx;
    int arow = tid >> 2, acol = (tid & 3) * 4;
    int brow = tid >> 4, bcol = (tid & 15) * 4;
    int rowBase = blockIdx.y * BM, colBase = blockIdx.x * BN;
    float acc[4][4] = {};
    for (int k0 = 0; k0 < Hh; k0 += BK) {
        float4 a = *(const float4*)(A + (size_t)(rowBase + arow) * Hh + k0 + acol);
        As[acol+0][arow] = a.x; As[acol+1][arow] = a.y;
        As[acol+2][arow] = a.z; As[acol+3][arow] = a.w;
        *(float4*)&Bs[brow][bcol] =
            *(const float4*)(Bm + (size_t)(k0 + brow) * Hh + colBase + bcol);
        __syncthreads();
        #pragma unroll
        for (int kk = 0; kk < BK; kk++) {
            float4 av = *(float4*)&As[kk][ty * 4];
            float4 bv = *(float4*)&Bs[kk][tx * 4];
            float ar[4] = {av.x, av.y, av.z, av.w};
            float br[4] = {bv.x, bv.y, bv.z, bv.w};
            #pragma unroll
            for (int i = 0; i < 4; i++)
                #pragma unroll
                for (int j = 0; j < 4; j++) acc[i][j] += ar[i] * br[j];
        }
        __syncthreads();
    }
    #pragma unroll
    for (int i = 0; i < 4; i++) {
        float4 o = make_float4(acc[i][0], acc[i][1], acc[i][2], acc[i][3]);
        *(float4*)(C + (size_t)(rowBase + ty * 4 + i) * Hh + colBase + tx * 4) = o;
    }
}

// WO with residual: h = x + ao @ wo
__global__ void k_wo(const float* __restrict__ wo, const float* __restrict__ x) {
    const float* A = g_ao;
    __shared__ float As[BK][BM];
    __shared__ float Bs[BK][BN];
    int tx = threadIdx.x, ty = threadIdx.y;
    int tid = ty * 16 + tx;
    int arow = tid >> 2, acol = (tid & 3) * 4;
    int brow = tid >> 4, bcol = (tid & 15) * 4;
    int rowBase = blockIdx.y * BM, colBase = blockIdx.x * BN;
    float acc[4][4] = {};
    for (int k0 = 0; k0 < Hh; k0 += BK) {
        float4 a = *(const float4*)(A + (size_t)(rowBase + arow) * Hh + k0 + acol);
        As[acol+0][arow] = a.x; As[acol+1][arow] = a.y;
        As[acol+2][arow] = a.z; As[acol+3][arow] = a.w;
        *(float4*)&Bs[brow][bcol] =
            *(const float4*)(wo + (size_t)(k0 + brow) * Hh + colBase + bcol);
        __syncthreads();
        #pragma unroll
        for (int kk = 0; kk < BK; kk++) {
            float4 av = *(float4*)&As[kk][ty * 4];
            float4 bv = *(float4*)&Bs[kk][tx * 4];
            float ar[4] = {av.x, av.y, av.z, av.w};
            float br[4] = {bv.x, bv.y, bv.z, bv.w};
            #pragma unroll
            for (int i = 0; i < 4; i++)
                #pragma unroll
                for (int j = 0; j < 4; j++) acc[i][j] += ar[i] * br[j];
        }
        __syncthreads();
    }
    #pragma unroll
    for (int i = 0; i < 4; i++) {
        size_t ro = (size_t)(rowBase + ty * 4 + i) * Hh + colBase + tx * 4;
        float4 xv = *(const float4*)(x + ro);
        float4 o = make_float4(acc[i][0] + xv.x, acc[i][1] + xv.y,
                               acc[i][2] + xv.z, acc[i][3] + xv.w);
        *(float4*)(g_h + ro) = o;
    }
}

// ---------------- attention: one warp per (b, head, query row) ----------------
__device__ __forceinline__ void attn_update(float s, float vx, float vy,
                                            float& m, float& l, float& ax, float& ay) {
    float mn = fmaxf(m, s);
    float sc = __expf(m - mn);
    float p  = __expf(s - mn);
    l  = l * sc + p;
    ax = ax * sc + p * vx;
    ay = ay * sc + p * vy;
    m  = mn;
}

__global__ void k_attn() {
    int gw   = (blockIdx.x * blockDim.x + threadIdx.x) >> 5;
    int lane = threadIdx.x & 31;
    if (gw >= Bb * NHh * Ss) return;
    int qi   = gw & (Ss - 1);
    int bh   = gw >> 10;
    int head = bh & (NHh - 1);
    int b    = bh >> 4;
    float2 qv = *(const float2*)(g_q + (size_t)(b * Ss + qi) * Hh + head * HDd + 2 * lane);
    qv.x *= 0.125f; qv.y *= 0.125f;          // 1/sqrt(64)
    const float* kb = g_k + ((size_t)b * Ss * Hh + head * HDd + 2 * lane);
    const float* vb = g_v + ((size_t)b * Ss * Hh + head * HDd + 2 * lane);
    float m = -1e30f, l = 0.f, ax = 0.f, ay = 0.f;
    int nk = qi + 1;
    int j = 0;
    for (; j + 4 <= nk; j += 4) {
        float2 k0 = *(const float2*)(kb + (size_t)(j + 0) * Hh);
        float2 k1 = *(const float2*)(kb + (size_t)(j + 1) * Hh);
        float2 k2 = *(const float2*)(kb + (size_t)(j + 2) * Hh);
        float2 k3 = *(const float2*)(kb + (size_t)(j + 3) * Hh);
        float s0 = qv.x * k0.x + qv.y * k0.y;
        float s1 = qv.x * k1.x + qv.y * k1.y;
        float s2 = qv.x * k2.x + qv.y * k2.y;
        float s3 = qv.x * k3.x + qv.y * k3.y;
        #pragma unroll
        for (int o = 16; o > 0; o >>= 1) {
            s0 += __shfl_xor_sync(0xffffffffu, s0, o);
            s1 += __shfl_xor_sync(0xffffffffu, s1, o);
            s2 += __shfl_xor_sync(0xffffffffu, s2, o);
            s3 += __shfl_xor_sync(0xffffffffu, s3, o);
        }
        float2 v0 = *(const float2*)(vb + (size_t)(j + 0) * Hh);
        float2 v1 = *(const float2*)(vb + (size_t)(j + 1) * Hh);
        float2 v2 = *(const float2*)(vb + (size_t)(j + 2) * Hh);
        float2 v3 = *(const float2*)(vb + (size_t)(j + 3) * Hh);
        attn_update(s0, v0.x, v0.y, m, l, ax, ay);
        attn_update(s1, v1.x, v1.y, m, l, ax, ay);
        attn_update(s2, v2.x, v2.y, m, l, ax, ay);
        attn_update(s3, v3.x, v3.y, m, l, ax, ay);
    }
    for (; j < nk; j++) {
        float2 kvv = *(const float2*)(kb + (size_t)j * Hh);
        float s = qv.x * kvv.x + qv.y * kvv.y;
        #pragma unroll
        for (int o = 16; o > 0; o >>= 1) s += __shfl_xor_sync(0xffffffffu, s, o);
        float2 vv = *(const float2*)(vb + (size_t)j * Hh);
        attn_update(s, vv.x, vv.y, m, l, ax, ay);
    }
    float inv = 1.f / l;
    float2 o = make_float2(ax * inv, ay * inv);
    *(float2*)(g_ao + (size_t)(b * Ss + qi) * Hh + head * HDd + 2 * lane) = o;
}

// ---------------- router: one warp per token ----------------
__global__ void k_router(const float* __restrict__ rw) {
    int t    = (blockIdx.x * blockDim.x + threadIdx.x) >> 5;
    int lane = threadIdx.x & 31;
    if (t >= Tt) return;
    const float* xr = g_hn + (size_t)t * Hh;
    float acc[Ee] = {};
    for (int hh = lane; hh < Hh; hh += 32) {
        float xv = xr[hh];
        #pragma unroll
        for (int e = 0; e < Ee; e++) acc[e] += xv * rw[hh * Ee + e];
    }
    #pragma unroll
    for (int e = 0; e < Ee; e++)
        #pragma unroll
        for (int o = 16; o > 0; o >>= 1) acc[e] += __shfl_xor_sync(0xffffffffu, acc[e], o);
    if (lane == 0) {
        float mx = acc[0];
        #pragma unroll
        for (int e = 1; e < Ee; e++) mx = fmaxf(mx, acc[e]);
        float p[Ee], s = 0.f;
        #pragma unroll
        for (int e = 0; e < Ee; e++) { p[e] = __expf(acc[e] - mx); s += p[e]; }
        float invs = 1.f / s;
        #pragma unroll
        for (int e = 0; e < Ee; e++) p[e] *= invs;
        int i1 = 0; float v1 = p[0];
        #pragma unroll
        for (int e = 1; e < Ee; e++) if (p[e] > v1) { v1 = p[e]; i1 = e; }
        int i2 = -1; float v2 = -1.f;
        #pragma unroll
        for (int e = 0; e < Ee; e++) if (e != i1 && p[e] > v2) { v2 = p[e]; i2 = e; }
        float inv = 1.f / (v1 + v2);
        g_topi[t * 2]     = i1; g_topi[t * 2 + 1] = i2;
        g_topw[t * 2]     = v1 * inv; g_topw[t * 2 + 1] = v2 * inv;
        atomicAdd(&g_cnt[i1], 1); atomicAdd(&g_cnt[i2], 1);
    }
}

__global__ void k_scan() {
    if (threadIdx.x == 0) {
        int o = 0;
        for (int e = 0; e < Ee; e++) { g_off[e] = o; o += g_cnt[e]; g_fill[e] = 0; }
    }
}

__global__ void k_fill() {
    int t = blockIdx.x * blockDim.x + threadIdx.x;
    if (t >= Tt) return;
    for (int kk = 0; kk < 2; kk++) {
        int e = g_topi[t * 2 + kk];
        int pos = atomicAdd(&g_fill[e], 1);
        int slot = g_off[e] + pos;
        g_tok[slot] = t;
        g_slot[t * 2 + kk] = slot;
    }
}

// ---------------- MoE GEMM 1: act = silu(hn@w1) * (hn@w3), gathered rows ----------------
__global__ void k_moe1(const float* __restrict__ w1, const float* __restrict__ w3) {
    int e = blockIdx.z;
    int cnt = g_cnt[e], base = g_off[e];
    int rtile = blockIdx.y * BM;
    if (rtile >= cnt) return;
    const float* B1 = w1 + (size_t)e * Hh * Ii;
    const float* B3 = w3 + (size_t)e * Hh * Ii;
    __shared__ float As[BK][BM];
    __shared__ float Bs1[BK][BN];
    __shared__ float Bs3[BK][BN];
    int tx = threadIdx.x, ty = threadIdx.y;
    int tid = ty * 16 + tx;
    int arow = tid >> 2, acol = (tid & 3) * 4;
    int brow = tid >> 4, bcol = (tid & 15) * 4;
    int colBase = blockIdx.x * BN;
    bool validA = (rtile + arow) < cnt;
    int tok = validA ? g_tok[base + rtile + arow] : g_tok[base];
    const float* Aptr = g_hn + (size_t)tok * Hh;
    float acc1[4][4] = {}, acc3[4][4] = {};
    for (int k0 = 0; k0 < Hh; k0 += BK) {
        float4 a = *(const float4*)(Aptr + k0 + acol);
        As[acol+0][arow] = a.x; As[acol+1][arow] = a.y;
        As[acol+2][arow] = a.z; As[acol+3][arow] = a.w;
        *(float4*)&Bs1[brow][bcol] =
            *(const float4*)(B1 + (size_t)(k0 + brow) * Ii + colBase + bcol);
        *(float4*)&Bs3[brow][bcol] =
            *(const float4*)(B3 + (size_t)(k0 + brow) * Ii + colBase + bcol);
        __syncthreads();
        #pragma unroll
        for (int kk = 0; kk < BK; kk++) {
            float4 av = *(float4*)&As[kk][ty * 4];
            float4 b1v = *(float4*)&Bs1[kk][tx * 4];
            float4 b3v = *(float4*)&Bs3[kk][tx * 4];
            float ar[4] = {av.x, av.y, av.z, av.w};
            float b1r[4] = {b1v.x, b1v.y, b1v.z, b1v.w};
            float b3r[4] = {b3v.x, b3v.y, b3v.z, b3v.w};
            #pragma unroll
            for (int i = 0; i < 4; i++)
                #pragma unroll
                for (int j = 0; j < 4; j++) {
                    acc1[i][j] += ar[i] * b1r[j];
                    acc3[i][j] += ar[i] * b3r[j];
                }
        }
        __syncthreads();
    }
    #pragma unroll
    for (int i = 0; i < 4; i++) {
        int rloc = rtile + ty * 4 + i;
        if (rloc >= cnt) continue;
        float4 o;
        float* op = &o.x;
        #pragma unroll
        for (int j = 0; j < 4; j++) {
            float h1 = acc1[i][j], h3 = acc3[i][j];
            op[j] = (h1 / (1.f + __expf(-h1))) * h3;
        }
        *(float4*)(g_act + (size_t)(base + rloc) * Ii + colBase + tx * 4) = o;
    }
}

// ---------------- MoE GEMM 2: y = act @ w2[e] ----------------
__global__ void k_moe2(const float* __restrict__ w2) {
    int e = blockIdx.z;
    int cnt = g_cnt[e], base = g_off[e];
    int rtile = blockIdx.y * BM;
    if (rtile >= cnt) return;
    const float* Bm = w2 + (size_t)e * Ii * Hh;
    __shared__ float As[BK][BM];
    __shared__ float Bs[BK][BN];
    int tx = threadIdx.x, ty = threadIdx.y;
    int tid = ty * 16 + tx;
    int arow = tid >> 2, acol = (tid & 3) * 4;
    int brow = tid >> 4, bcol = (tid & 15) * 4;
    int colBase = blockIdx.x * BN;
    bool validA = (rtile + arow) < cnt;
    int rowIdx = validA ? (base + rtile + arow) : base;
    const float* Aptr = g_act + (size_t)rowIdx * Ii;
    float acc[4][4] = {};
    for (int k0 = 0; k0 < Ii; k0 += BK) {
        float4 a = *(const float4*)(Aptr + k0 + acol);
        As[acol+0][arow] = a.x; As[acol+1][arow] = a.y;
        As[acol+2][arow] = a.z; As[acol+3][arow] = a.w;
        *(float4*)&Bs[brow][bcol] =
            *(const float4*)(Bm + (size_t)(k0 + brow) * Hh + colBase + bcol);
        __syncthreads();
        #pragma unroll
        for (int kk = 0; kk < BK; kk++) {
            float4 av = *(float4*)&As[kk][ty * 4];
            float4 bv = *(float4*)&Bs[kk][tx * 4];
            float ar[4] = {av.x, av.y, av.z, av.w};
            float br[4] = {bv.x, bv.y, bv.z, bv.w};
            #pragma unroll
            for (int i = 0; i < 4; i++)
                #pragma unroll
                for (int j = 0; j < 4; j++) acc[i][j] += ar[i] * br[j];
        }
        __syncthreads();
    }
    #pragma unroll
    for (int i = 0; i < 4; i++) {
        int rloc = rtile + ty * 4 + i;
        if (rloc >= cnt) continue;
        float4 o = make_float4(acc[i][0], acc[i][1], acc[i][2], acc[i][3]);
        *(float4*)(g_y + (size_t)(base + rloc) * Hh + colBase + tx * 4) = o;
    }
}

// ---------------- combine: out = h + w0*y[slot0] + w1*y[slot1] ----------------
__global__ void k_combine(float* __restrict__ out) {
    int t = blockIdx.x;
    int i = threadIdx.x;                 // 256 threads * float4 = 1024
    int s0 = g_slot[t * 2], s1 = g_slot[t * 2 + 1];
    float w0 = g_topw[t * 2], w1 = g_topw[t * 2 + 1];
    float4 hv = ((const float4*)g_h)[(size_t)t * 256 + i];
    float4 y0 = ((const float4*)g_y)[(size_t)s0 * 256 + i];
    float4 y1 = ((const float4*)g_y)[(size_t)s1 * 256 + i];
    float4 o;
    o.x = hv.x + w0 * y0.x + w1 * y1.x;
    o.y = hv.y + w0 * y0.y + w1 * y1.y;
    o.z = hv.z + w0 * y0.z + w1 * y1.z;
    o.w = hv.w + w0 * y0.w + w1 * y1.w;
    ((float4*)out)[(size_t)t * 256 + i] = o;
}

// ---------------- launch ----------------
extern "C" void kernel_launch(void* const* d_in, const int* in_sizes, int n_in,
                              void* d_out, int out_size) {
    const float* x    = (const float*)d_in[0];
    const float* anw  = (const float*)d_in[1];
    const float* fnw  = (const float*)d_in[2];
    const float* wq   = (const float*)d_in[3];
    const float* wk   = (const float*)d_in[4];
    const float* wv   = (const float*)d_in[5];
    const float* wo   = (const float*)d_in[6];
    const float* rw   = (const float*)d_in[7];
    const float* w1   = (const float*)d_in[8];
    const float* w3   = (const float*)d_in[9];
    const float* w2   = (const float*)d_in[10];
    const float* fc   = (const float*)d_in[11];
    float* out = (float*)d_out;

    float* d_xn; cudaGetSymbolAddress((void**)&d_xn, g_xn);
    float* d_h;  cudaGetSymbolAddress((void**)&d_h,  g_h);
    float* d_hn; cudaGetSymbolAddress((void**)&d_hn, g_hn);

    dim3 tb(16, 16);

    k_zero<<<1, 32>>>();
    k_rmsnorm<<<Tt, 256>>>(x, anw, d_xn);
    k_qkv<<<dim3(Hh / BN, Tt / BM, 3), tb>>>(wq, wk, wv);
    k_rope<<<dim3((Tt * NHh * 32) / 256, 2), 256>>>(fc);
    k_attn<<<(Bb * NHh * Ss) / 4, 128>>>();
    k_wo<<<dim3(Hh / BN, Tt / BM), tb>>>(wo, x);
    k_rmsnorm<<<Tt, 256>>>(d_h, fnw, d_hn);
    k_router<<<Tt / 8, 256>>>(rw);
    k_scan<<<1, 32>>>();
    k_fill<<<Tt / 256, 256>>>();
    k_moe1<<<dim3(Ii / BN, Tt / BM, Ee), tb>>>(w1, w3);
    k_moe2<<<dim3(Hh / BN, Tt / BM, Ee), tb>>>(w2);
    k_combine<<<Tt, 256>>>(out);
}